// round 16
// baseline (speedup 1.0000x reference)
#include <cuda_runtime.h>
#include <cuda_fp16.h>
#include <cstdint>
#include <cstddef>

// Problem dims (fixed by the dataset)
#define NB    8
#define TT    256
#define UU    64
#define JD    512
#define VOCAB 1024
#define MTOT  (NB * TT * UU)                    // 131072 joint rows

// Scratch (device globals: no allocation allowed)
__device__ float g_enc_p[NB * TT * JD];                 // (b*T+t, j)  2048 x 512
__device__ float g_pred_p[NB * UU * JD];                // (b*U+u, j)   512 x 512
__device__ __align__(16) __half g_Wh[VOCAB * JD];       // W_joint^T fp16, [v][j]
__device__ __align__(16) __half g_H[(size_t)MTOT * JD]; // tanh(enc⊕pred) fp16, 134 MB
__device__ __align__(16) __half g_Eh[NB * TT * JD];     // enc_out fp16   [m][512]
__device__ __align__(16) __half g_Ph[NB * UU * 640];    // pred_out fp16  [m][640]
__device__ __align__(16) __half g_WEt[JD * JD];         // W_enc^T fp16   [n][512]
__device__ __align__(16) __half g_WPt[JD * 640];        // W_pred^T fp16  [n][640]

__device__ __forceinline__ float tanh_fast(float x) {
    float y;
    asm("tanh.approx.f32 %0, %1;" : "=f"(y) : "f"(x));
    return y;
}

__device__ __forceinline__ uint32_t smem_u32(const void* p) {
    uint32_t a;
    asm("{ .reg .u64 t; cvta.to.shared.u64 t, %1; cvt.u32.u64 %0, t; }" : "=r"(a) : "l"(p));
    return a;
}

__device__ __forceinline__ void ldsm4(uint4& v, uint32_t a) {
    asm volatile("ldmatrix.sync.aligned.m8n8.x4.shared.b16 {%0,%1,%2,%3}, [%4];"
                 : "=r"(v.x), "=r"(v.y), "=r"(v.z), "=r"(v.w) : "r"(a));
}

__device__ __forceinline__ void mma_fp16(float (&d)[4], const uint4& a,
                                         uint32_t b0, uint32_t b1) {
    asm volatile(
        "mma.sync.aligned.m16n8k16.row.col.f32.f16.f16.f32 "
        "{%0,%1,%2,%3},{%4,%5,%6,%7},{%8,%9},{%0,%1,%2,%3};"
        : "+f"(d[0]), "+f"(d[1]), "+f"(d[2]), "+f"(d[3])
        : "r"(a.x), "r"(a.y), "r"(a.z), "r"(a.w), "r"(b0), "r"(b1));
}

// ---------------------------------------------------------------------------
// One-shot conversions (fp32 -> fp16, transposes for B operands).
// blockIdx ranges: [0,4096) enc ; [4096,5376) pred ; [5376,6400) We^T ;
// [6400,7680) Wp^T ; [7680,9728) Wj^T.
// ---------------------------------------------------------------------------
__global__ __launch_bounds__(256)
void prep_all(const float* __restrict__ enc, const float* __restrict__ pred,
              const float* __restrict__ We, const float* __restrict__ Wp,
              const float* __restrict__ Wj)
{
    int b = blockIdx.x;
    int t = threadIdx.x;
    if (b < 4096) {                       // enc_out: 2048x512 contiguous
        int idx = b * 256 + t;
        g_Eh[idx] = __float2half_rn(enc[idx]);
    } else if (b < 5376) {                // pred_out: 512x640 contiguous
        int idx = (b - 4096) * 256 + t;
        g_Ph[idx] = __float2half_rn(pred[idx]);
    } else if (b < 6400) {                // W_enc [k][n] -> [n][k], 512x512
        int idx = (b - 5376) * 256 + t;
        int k = idx >> 9, n = idx & 511;
        g_WEt[n * JD + k] = __float2half_rn(We[idx]);
    } else if (b < 7680) {                // W_pred [k][n] 640x512 -> [n=512][k=640]
        int idx = (b - 6400) * 256 + t;
        int k = idx >> 9, n = idx & 511;
        g_WPt[n * 640 + k] = __float2half_rn(Wp[idx]);
    } else {                              // W_joint [j][v] 512x1024 -> [v][j]
        int idx = (b - 7680) * 256 + t;
        int j = idx >> 10, v = idx & 1023;
        g_Wh[(size_t)v * JD + j] = __float2half_rn(Wj[idx]);
    }
}

// ---------------------------------------------------------------------------
// Shared fp16-MMA mainloop constants (proven in joint_mma R15)
// ---------------------------------------------------------------------------
#define STRD 24                      // halves per SMEM row (48 B) - LDSM conflict-free
#define KC2  16
#define A_H  (128 * STRD)            // 3072 halves per operand tile
#define STG_H (2 * A_H)              // A + B per stage = 6144 halves
#define STG_BYTES (STG_H * 2)        // 12288 bytes per stage
#define NSTG 3

// ---------------------------------------------------------------------------
// Tensor-core projections: C = A @ W^T + bias  (fp16 in, f32 out)
// yy in [0,16): enc  M=2048 K=512 ; yy in [16,20): pred M=512 K=640. N=512.
// Same 3-stage / prefetch-distance-2 schedule as joint_mma.
// ---------------------------------------------------------------------------
__global__ __launch_bounds__(256, 2)
void proj_tc(const float* __restrict__ be, const float* __restrict__ bp)
{
    __shared__ __align__(16) __half smh[NSTG * STG_H];
    const uint32_t smb = smem_u32(smh);
    const int tid = threadIdx.x;
    const int wid = tid >> 5, lid = tid & 31;
    const int wm = wid & 3, wn = wid >> 2;
    const int r = lid >> 2, c = lid & 3;
    const int col0 = blockIdx.x << 7;
    const int yy = blockIdx.y;

    const __half *Asrc0, *Bsrc0;
    float* C;
    const float* bias;
    int Kd, nch, row0;
    if (yy < 16) { Asrc0 = g_Eh; Bsrc0 = g_WEt; C = g_enc_p;  bias = be; Kd = 512; nch = 32; row0 = yy << 7; }
    else         { Asrc0 = g_Ph; Bsrc0 = g_WPt; C = g_pred_p; bias = bp; Kd = 640; nch = 40; row0 = (yy - 16) << 7; }

    float acc[2][8][4];
    #pragma unroll
    for (int mt = 0; mt < 2; mt++)
        #pragma unroll
        for (int nt = 0; nt < 8; nt++)
            #pragma unroll
            for (int q = 0; q < 4; q++) acc[mt][nt][q] = 0.0f;

    const int rA = (lid & 7) + ((lid >> 3) & 1) * 8;
    const int kA = (lid >> 4) * 8;
    const uint32_t aBase = smb + 2 * ((wm * 32 + rA) * STRD + kA);
    const int rB = (lid & 7) + (lid >> 4) * 8;
    const int kB = ((lid >> 3) & 1) * 8;
    const uint32_t bBase = smb + 2 * (A_H + (wn * 64 + rB) * STRD + kB);

    const int ldRow = tid >> 1;
    const int ldC   = (tid & 1) * 8;
    const __half* srcA = Asrc0 + (size_t)(row0 + ldRow) * Kd + ldC;
    const __half* srcB = Bsrc0 + (size_t)(col0 + ldRow) * Kd + ldC;
    const uint32_t dstA = smb + 2 * (uint32_t)(ldRow * STRD + ldC);
    const uint32_t dstB = dstA + 2 * A_H;

    auto loadStage = [&](int buf, int k0) {
        uint32_t so = (uint32_t)buf * STG_BYTES;
        asm volatile("cp.async.cg.shared.global [%0], [%1], 16;"
                     :: "r"(dstA + so), "l"(srcA + k0) : "memory");
        asm volatile("cp.async.cg.shared.global [%0], [%1], 16;"
                     :: "r"(dstB + so), "l"(srcB + k0) : "memory");
        asm volatile("cp.async.commit_group;" ::: "memory");
    };

    loadStage(0, 0);
    loadStage(1, KC2);

    int cbuf = 0, pbuf = 2;
    for (int ch = 0; ch < nch; ch++) {
        if (ch < nch - 1) {
            asm volatile("cp.async.wait_group 1;" ::: "memory");
        } else {
            asm volatile("cp.async.wait_group 0;" ::: "memory");
        }
        __syncthreads();
        if (ch + 2 < nch) loadStage(pbuf, (ch + 2) * KC2);

        const uint32_t so = (uint32_t)cbuf * STG_BYTES;
        uint4 av[2];
        #pragma unroll
        for (int mt = 0; mt < 2; mt++)
            ldsm4(av[mt], aBase + so + (uint32_t)(mt * 16 * STRD) * 2);
        #pragma unroll
        for (int p = 0; p < 4; p++) {
            uint4 bv;
            ldsm4(bv, bBase + so + (uint32_t)(p * 16 * STRD) * 2);
            #pragma unroll
            for (int mt = 0; mt < 2; mt++) {
                mma_fp16(acc[mt][2 * p],     av[mt], bv.x, bv.y);
                mma_fp16(acc[mt][2 * p + 1], av[mt], bv.z, bv.w);
            }
        }
        cbuf = (cbuf == NSTG - 1) ? 0 : cbuf + 1;
        pbuf = (pbuf == NSTG - 1) ? 0 : pbuf + 1;
    }

    // epilogue: bias add + f32 store (row stride 512)
    float2 bv[8];
    #pragma unroll
    for (int nt = 0; nt < 8; nt++)
        bv[nt] = *(const float2*)(bias + col0 + wn * 64 + nt * 8 + c * 2);

    #pragma unroll
    for (int mt = 0; mt < 2; mt++)
        #pragma unroll
        for (int h = 0; h < 2; h++) {
            int grow = row0 + wm * 32 + mt * 16 + h * 8 + r;
            float* op = C + (size_t)grow * JD + col0 + wn * 64 + c * 2;
            #pragma unroll
            for (int nt = 0; nt < 8; nt++) {
                float2 o;
                o.x = acc[mt][nt][2 * h]     + bv[nt].x;
                o.y = acc[mt][nt][2 * h + 1] + bv[nt].y;
                *(float2*)(op + nt * 8) = o;
            }
        }
}

// ---------------------------------------------------------------------------
// H = fp16(tanh(enc_p ⊕ pred_p)); one thread = 8 consecutive j's of one row.
// ---------------------------------------------------------------------------
__global__ __launch_bounds__(256)
void tanh_h()
{
    int idx = blockIdx.x * 256 + threadIdx.x;   // 0 .. MTOT*64-1
    int gm = idx >> 6;
    int j0 = (idx & 63) * 8;
    const float* er = g_enc_p  + (size_t)(gm >> 6) * JD + j0;
    const float* pr = g_pred_p + (size_t)((gm >> 14) * UU + (gm & 63)) * JD + j0;
    float4 e0 = *(const float4*)er;
    float4 p0 = *(const float4*)pr;
    float4 e1 = *(const float4*)(er + 4);
    float4 p1 = *(const float4*)(pr + 4);
    __half2 h0 = __floats2half2_rn(tanh_fast(e0.x + p0.x), tanh_fast(e0.y + p0.y));
    __half2 h1 = __floats2half2_rn(tanh_fast(e0.z + p0.z), tanh_fast(e0.w + p0.w));
    __half2 h2 = __floats2half2_rn(tanh_fast(e1.x + p1.x), tanh_fast(e1.y + p1.y));
    __half2 h3 = __floats2half2_rn(tanh_fast(e1.z + p1.z), tanh_fast(e1.w + p1.w));
    uint4 v = make_uint4(*(uint32_t*)&h0, *(uint32_t*)&h1, *(uint32_t*)&h2, *(uint32_t*)&h3);
    *(uint4*)(g_H + (size_t)gm * JD + j0) = v;
}

// ---------------------------------------------------------------------------
// Joint GEMM (UNCHANGED from R15 — at ~98% of the mma.sync fp16 ceiling):
// out = H @ Wh^T + bj.  M=131072, N=1024, K=512.
// ---------------------------------------------------------------------------
#define NCHUNK (JD / KC2)            // 32

__global__ __launch_bounds__(256, 2)
void joint_mma(const float* __restrict__ bj, float* __restrict__ out)
{
    __shared__ __align__(16) __half smh[NSTG * STG_H];   // 36864 B static
    const uint32_t smb = smem_u32(smh);
    const int tid = threadIdx.x;
    const int wid = tid >> 5, lid = tid & 31;
    const int wm = wid & 3, wn = wid >> 2;
    const int r = lid >> 2, c = lid & 3;
    const int col0 = blockIdx.x << 7;
    const size_t gm0 = (size_t)blockIdx.y * 128;

    float acc[2][8][4];
    #pragma unroll
    for (int mt = 0; mt < 2; mt++)
        #pragma unroll
        for (int nt = 0; nt < 8; nt++)
            #pragma unroll
            for (int q = 0; q < 4; q++) acc[mt][nt][q] = 0.0f;

    const int rA = (lid & 7) + ((lid >> 3) & 1) * 8;
    const int kA = (lid >> 4) * 8;
    const uint32_t aBase = smb + 2 * ((wm * 32 + rA) * STRD + kA);
    const int rB = (lid & 7) + (lid >> 4) * 8;
    const int kB = ((lid >> 3) & 1) * 8;
    const uint32_t bBase = smb + 2 * (A_H + (wn * 64 + rB) * STRD + kB);

    const int ldRow = tid >> 1;
    const int ldC   = (tid & 1) * 8;
    const __half* srcA = g_H  + (gm0 + ldRow) * JD + ldC;
    const __half* srcB = g_Wh + (size_t)(col0 + ldRow) * JD + ldC;
    const uint32_t dstA = smb + 2 * (uint32_t)(ldRow * STRD + ldC);
    const uint32_t dstB = dstA + 2 * A_H;

    auto loadStage = [&](int buf, int k0) {
        uint32_t so = (uint32_t)buf * STG_BYTES;
        asm volatile("cp.async.cg.shared.global [%0], [%1], 16;"
                     :: "r"(dstA + so), "l"(srcA + k0) : "memory");
        asm volatile("cp.async.cg.shared.global [%0], [%1], 16;"
                     :: "r"(dstB + so), "l"(srcB + k0) : "memory");
        asm volatile("cp.async.commit_group;" ::: "memory");
    };

    loadStage(0, 0);
    loadStage(1, KC2);

    int cbuf = 0, pbuf = 2;
    for (int ch = 0; ch < NCHUNK; ch++) {
        if (ch < NCHUNK - 1) {
            asm volatile("cp.async.wait_group 1;" ::: "memory");
        } else {
            asm volatile("cp.async.wait_group 0;" ::: "memory");
        }
        __syncthreads();
        if (ch + 2 < NCHUNK) loadStage(pbuf, (ch + 2) * KC2);

        const uint32_t so = (uint32_t)cbuf * STG_BYTES;
        uint4 av[2];
        #pragma unroll
        for (int mt = 0; mt < 2; mt++)
            ldsm4(av[mt], aBase + so + (uint32_t)(mt * 16 * STRD) * 2);
        #pragma unroll
        for (int p = 0; p < 4; p++) {
            uint4 bv;
            ldsm4(bv, bBase + so + (uint32_t)(p * 16 * STRD) * 2);
            #pragma unroll
            for (int mt = 0; mt < 2; mt++) {
                mma_fp16(acc[mt][2 * p],     av[mt], bv.x, bv.y);
                mma_fp16(acc[mt][2 * p + 1], av[mt], bv.z, bv.w);
            }
        }
        cbuf = (cbuf == NSTG - 1) ? 0 : cbuf + 1;
        pbuf = (pbuf == NSTG - 1) ? 0 : pbuf + 1;
    }

    float2 bv[8];
    #pragma unroll
    for (int nt = 0; nt < 8; nt++)
        bv[nt] = *(const float2*)(bj + col0 + wn * 64 + nt * 8 + c * 2);

    #pragma unroll
    for (int mt = 0; mt < 2; mt++)
        #pragma unroll
        for (int h = 0; h < 2; h++) {
            int grow = wm * 32 + mt * 16 + h * 8 + r;
            float* op = out + (gm0 + grow) * VOCAB + col0 + wn * 64 + c * 2;
            #pragma unroll
            for (int nt = 0; nt < 8; nt++) {
                float2 o;
                o.x = acc[mt][nt][2 * h]     + bv[nt].x;
                o.y = acc[mt][nt][2 * h + 1] + bv[nt].y;
                *(float2*)(op + nt * 8) = o;
            }
        }
}

// ---------------------------------------------------------------------------
extern "C" void kernel_launch(void* const* d_in, const int* in_sizes, int n_in,
                              void* d_out, int out_size)
{
    (void)in_sizes; (void)n_in; (void)out_size;
    const float* enc_out  = (const float*)d_in[0];  // (8,256,512)
    const float* pred_out = (const float*)d_in[1];  // (8,64,640)
    const float* W_enc    = (const float*)d_in[2];  // (512,512)
    const float* b_enc    = (const float*)d_in[3];  // (512)
    const float* W_pred   = (const float*)d_in[4];  // (640,512)
    const float* b_pred   = (const float*)d_in[5];  // (512)
    const float* W_joint  = (const float*)d_in[6];  // (512,1024)
    const float* b_joint  = (const float*)d_in[7];  // (1024)
    float* out = (float*)d_out;                     // (8,256,64,1024)

    prep_all<<<9728, 256>>>(enc_out, pred_out, W_enc, W_pred, W_joint);
    proj_tc<<<dim3(4, 20), 256>>>(b_enc, b_pred);
    tanh_h<<<(MTOT * 64) / 256, 256>>>();
    joint_mma<<<dim3(VOCAB / 128, MTOT / 128), 256>>>(b_joint, out);
}